// round 1
// baseline (speedup 1.0000x reference)
#include <cuda_runtime.h>
#include <math.h>

#define NN 50000
#define NE 800000
#define ETOT (NE + NN)

// ---------------- scratch (static device globals; no allocation) -------------
__device__ float g_h1[(size_t)NN * 256];    // layer1 projected features [N,4,64]
__device__ float g_hact[(size_t)NN * 256];  // layer1 output after elu
__device__ float g_h2[(size_t)NN * 128];    // layer2 projected features
__device__ float g_as1[NN * 4];
__device__ float g_ad1[NN * 4];
__device__ float g_as2[NN];
__device__ float g_ad2[NN];
__device__ int   g_deg[NN];
__device__ int   g_off[NN + 1];
__device__ int   g_fill[NN];
__device__ int   g_csr[ETOT];
__device__ int   g_is64;

// ---------------- edge dtype detection (int32 vs int64) ----------------------
__global__ void detect_dtype_kernel(const int* __restrict__ e32, int E) {
    if (threadIdx.x == 0 && blockIdx.x == 0) {
        int acc = 0;
        int lim = (E > 1000) ? 1000 : E;
        for (int k = 0; k < lim; ++k) acc |= e32[2 * k + 1];
        g_is64 = (acc == 0) ? 1 : 0;   // int64 high words are all zero
    }
}

__device__ __forceinline__ int edge_src(const int* e32, const long long* e64, int E, int t) {
    if (t >= E) return t - E;                       // self loop
    return g_is64 ? (int)e64[t] : e32[t];
}
__device__ __forceinline__ int edge_dst(const int* e32, const long long* e64, int E, int t) {
    if (t >= E) return t - E;                       // self loop
    return g_is64 ? (int)e64[E + t] : e32[E + t];
}

// ---------------- CSR build ---------------------------------------------------
__global__ void zero_deg_kernel(int n) {
    int i = blockIdx.x * blockDim.x + threadIdx.x;
    if (i < n) g_deg[i] = 0;
}

__global__ void histo_kernel(const int* __restrict__ e32, const long long* __restrict__ e64,
                             int E, int n) {
    int t = blockIdx.x * blockDim.x + threadIdx.x;
    int tot = E + n;
    if (t < tot) {
        int d = edge_dst(e32, e64, E, t);
        atomicAdd(&g_deg[d], 1);
    }
}

// single-block exclusive scan of g_deg -> g_off / g_fill
__global__ void scan_kernel(int n) {
    __shared__ int sh[1024];
    int t = threadIdx.x;
    int C = (n + 1023) / 1024;
    int start = t * C;
    int end = start + C; if (end > n) end = n;
    int s = 0;
    for (int i = start; i < end; ++i) s += g_deg[i];
    sh[t] = s;
    __syncthreads();
    #pragma unroll
    for (int d = 1; d < 1024; d <<= 1) {
        int v = (t >= d) ? sh[t - d] : 0;
        __syncthreads();
        sh[t] += v;
        __syncthreads();
    }
    int excl = sh[t] - s;
    for (int i = start; i < end; ++i) {
        g_off[i]  = excl;
        g_fill[i] = excl;
        excl += g_deg[i];
    }
    if (t == 0) g_off[n] = sh[1023];
}

__global__ void scatter_kernel(const int* __restrict__ e32, const long long* __restrict__ e64,
                               int E, int n) {
    int t = blockIdx.x * blockDim.x + threadIdx.x;
    int tot = E + n;
    if (t < tot) {
        int s = edge_src(e32, e64, E, t);
        int d = edge_dst(e32, e64, E, t);
        int pos = atomicAdd(&g_fill[d], 1);
        g_csr[pos] = s;
    }
}

// ---------------- SGEMM: C[M,N] = A[M,K] @ B[K,N] (row major) ----------------
// BM=128, BN=64, BK=8, 256 threads, 8x4 micro-tile. N%64==0, K%8==0 required.
__global__ __launch_bounds__(256) void sgemm_kernel(
    const float* __restrict__ A, const float* __restrict__ B, float* __restrict__ C,
    int M, int N, int K)
{
    const int BM = 128, BN = 64, BK = 8;
    __shared__ float As[BK][BM];
    __shared__ float Bs[BK][BN];

    int tid = threadIdx.x;
    int tx = tid & 15;        // 0..15 -> 4 cols each
    int ty = tid >> 4;        // 0..15 -> 8 rows each
    int rowBase = blockIdx.y * BM;
    int colBase = blockIdx.x * BN;

    float acc[8][4];
    #pragma unroll
    for (int i = 0; i < 8; ++i)
        #pragma unroll
        for (int j = 0; j < 4; ++j) acc[i][j] = 0.f;

    int ar = tid >> 1;             // 0..127
    int ak = (tid & 1) * 4;        // 0 or 4

    for (int k0 = 0; k0 < K; k0 += BK) {
        int grow = rowBase + ar;
        float4 av = make_float4(0.f, 0.f, 0.f, 0.f);
        if (grow < M) av = *(const float4*)(A + (size_t)grow * K + k0 + ak);
        As[ak + 0][ar] = av.x;
        As[ak + 1][ar] = av.y;
        As[ak + 2][ar] = av.z;
        As[ak + 3][ar] = av.w;
        if (tid < 128) {
            int br = tid >> 4;          // 0..7
            int bc = (tid & 15) * 4;    // 0..60
            float4 bv = *(const float4*)(B + (size_t)(k0 + br) * N + colBase + bc);
            *(float4*)&Bs[br][bc] = bv;
        }
        __syncthreads();
        #pragma unroll
        for (int kk = 0; kk < BK; ++kk) {
            float4 a0 = *(const float4*)&As[kk][ty * 8];
            float4 a1 = *(const float4*)&As[kk][ty * 8 + 4];
            float4 b  = *(const float4*)&Bs[kk][tx * 4];
            float a[8] = {a0.x, a0.y, a0.z, a0.w, a1.x, a1.y, a1.z, a1.w};
            float bb[4] = {b.x, b.y, b.z, b.w};
            #pragma unroll
            for (int i = 0; i < 8; ++i)
                #pragma unroll
                for (int j = 0; j < 4; ++j) acc[i][j] = fmaf(a[i], bb[j], acc[i][j]);
        }
        __syncthreads();
    }

    #pragma unroll
    for (int i = 0; i < 8; ++i) {
        int r = rowBase + ty * 8 + i;
        if (r < M) {
            float4 v = make_float4(acc[i][0], acc[i][1], acc[i][2], acc[i][3]);
            *(float4*)(C + (size_t)r * N + colBase + tx * 4) = v;
        }
    }
}

// ---------------- per-node attention coefficients -----------------------------
// layer 1: 4 heads x 64 dims; one warp per node; lane owns cols lane*8..+7
__global__ __launch_bounds__(256) void alpha1_kernel(
    const float* __restrict__ a_src, const float* __restrict__ a_dst, int n)
{
    __shared__ float sa[256], sd[256];
    sa[threadIdx.x] = a_src[threadIdx.x];
    sd[threadIdx.x] = a_dst[threadIdx.x];
    __syncthreads();
    int node = (blockIdx.x << 3) + (threadIdx.x >> 5);
    if (node >= n) return;
    int lane = threadIdx.x & 31;
    int c0 = lane * 8;
    const float4* p = (const float4*)(g_h1 + (size_t)node * 256 + c0);
    float4 v0 = p[0], v1 = p[1];
    float hv[8] = {v0.x, v0.y, v0.z, v0.w, v1.x, v1.y, v1.z, v1.w};
    float ps = 0.f, pd = 0.f;
    #pragma unroll
    for (int j = 0; j < 8; ++j) {
        ps = fmaf(hv[j], sa[c0 + j], ps);
        pd = fmaf(hv[j], sd[c0 + j], pd);
    }
    // reduce within groups of 8 lanes (same head)
    #pragma unroll
    for (int o = 1; o < 8; o <<= 1) {
        ps += __shfl_xor_sync(0xffffffffu, ps, o);
        pd += __shfl_xor_sync(0xffffffffu, pd, o);
    }
    if ((lane & 7) == 0) {
        int h = lane >> 3;
        g_as1[node * 4 + h] = ps;
        g_ad1[node * 4 + h] = pd;
    }
}

// layer 2: 1 head x 128 dims; lane owns cols lane*4..+3
__global__ __launch_bounds__(256) void alpha2_kernel(
    const float* __restrict__ a_src, const float* __restrict__ a_dst, int n)
{
    __shared__ float sa[128], sd[128];
    if (threadIdx.x < 128) {
        sa[threadIdx.x] = a_src[threadIdx.x];
        sd[threadIdx.x] = a_dst[threadIdx.x];
    }
    __syncthreads();
    int node = (blockIdx.x << 3) + (threadIdx.x >> 5);
    if (node >= n) return;
    int lane = threadIdx.x & 31;
    int c0 = lane * 4;
    float4 v = *(const float4*)(g_h2 + (size_t)node * 128 + c0);
    float ps = v.x * sa[c0] + v.y * sa[c0 + 1] + v.z * sa[c0 + 2] + v.w * sa[c0 + 3];
    float pd = v.x * sd[c0] + v.y * sd[c0 + 1] + v.z * sd[c0 + 2] + v.w * sd[c0 + 3];
    #pragma unroll
    for (int o = 1; o < 32; o <<= 1) {
        ps += __shfl_xor_sync(0xffffffffu, ps, o);
        pd += __shfl_xor_sync(0xffffffffu, pd, o);
    }
    if (lane == 0) {
        g_as2[node] = ps;
        g_ad2[node] = pd;
    }
}

__device__ __forceinline__ float lrelu(float x) { return fmaxf(x, 0.2f * x); }

// ---------------- layer-1 aggregation: warp per node, softmax + weighted sum --
__global__ __launch_bounds__(256) void agg1_kernel(const float* __restrict__ b1, int n)
{
    int node = (blockIdx.x << 3) + (threadIdx.x >> 5);
    if (node >= n) return;
    int lane = threadIdx.x & 31;
    int s = g_off[node], e = g_off[node + 1];
    int h = lane >> 3;  // head owned by this lane

    float ad[4];
    #pragma unroll
    for (int hh = 0; hh < 4; ++hh) ad[hh] = g_ad1[node * 4 + hh];

    // pass 1: per-head max over incoming edges
    float mx[4] = {-1e30f, -1e30f, -1e30f, -1e30f};
    for (int i = s + lane; i < e; i += 32) {
        int src = g_csr[i];
        const float* asv = g_as1 + src * 4;
        #pragma unroll
        for (int hh = 0; hh < 4; ++hh) {
            float lg = lrelu(asv[hh] + ad[hh]);
            mx[hh] = fmaxf(mx[hh], lg);
        }
    }
    #pragma unroll
    for (int o = 16; o > 0; o >>= 1)
        #pragma unroll
        for (int hh = 0; hh < 4; ++hh)
            mx[hh] = fmaxf(mx[hh], __shfl_xor_sync(0xffffffffu, mx[hh], o));
    float mh = mx[h];
    float adh = ad[h];

    // pass 2: weighted accumulation; lane owns cols lane*8..lane*8+7 (all head h)
    float acc[8] = {0, 0, 0, 0, 0, 0, 0, 0};
    float denom = 0.f;
    for (int i = s; i < e; ++i) {
        int src = g_csr[i];
        float lg = lrelu(g_as1[src * 4 + h] + adh);
        float w = __expf(lg - mh);
        denom += w;
        const float4* p = (const float4*)(g_h1 + (size_t)src * 256 + lane * 8);
        float4 v0 = p[0], v1 = p[1];
        acc[0] = fmaf(w, v0.x, acc[0]);
        acc[1] = fmaf(w, v0.y, acc[1]);
        acc[2] = fmaf(w, v0.z, acc[2]);
        acc[3] = fmaf(w, v0.w, acc[3]);
        acc[4] = fmaf(w, v1.x, acc[4]);
        acc[5] = fmaf(w, v1.y, acc[5]);
        acc[6] = fmaf(w, v1.z, acc[6]);
        acc[7] = fmaf(w, v1.w, acc[7]);
    }
    float inv = 1.0f / (denom + 1e-16f);
    #pragma unroll
    for (int j = 0; j < 8; ++j) {
        int c = lane * 8 + j;
        float v = acc[j] * inv + b1[c];
        v = (v > 0.f) ? v : expm1f(v);  // elu
        g_hact[(size_t)node * 256 + c] = v;
    }
}

// ---------------- layer-2 aggregation + L2-normalize epilogue ------------------
__global__ __launch_bounds__(256) void agg2_kernel(
    const float* __restrict__ b2, float* __restrict__ out, int n)
{
    int node = (blockIdx.x << 3) + (threadIdx.x >> 5);
    if (node >= n) return;
    int lane = threadIdx.x & 31;
    int s = g_off[node], e = g_off[node + 1];

    float ad = g_ad2[node];
    float mx = -1e30f;
    for (int i = s + lane; i < e; i += 32) {
        int src = g_csr[i];
        mx = fmaxf(mx, lrelu(g_as2[src] + ad));
    }
    #pragma unroll
    for (int o = 16; o > 0; o >>= 1)
        mx = fmaxf(mx, __shfl_xor_sync(0xffffffffu, mx, o));

    float acc[4] = {0, 0, 0, 0};
    float denom = 0.f;
    for (int i = s; i < e; ++i) {
        int src = g_csr[i];
        float lg = lrelu(g_as2[src] + ad);
        float w = __expf(lg - mx);
        denom += w;
        float4 v = *(const float4*)(g_h2 + (size_t)src * 128 + lane * 4);
        acc[0] = fmaf(w, v.x, acc[0]);
        acc[1] = fmaf(w, v.y, acc[1]);
        acc[2] = fmaf(w, v.z, acc[2]);
        acc[3] = fmaf(w, v.w, acc[3]);
    }
    float inv = 1.0f / (denom + 1e-16f);
    float v[4];
    float ss = 0.f;
    #pragma unroll
    for (int j = 0; j < 4; ++j) {
        v[j] = acc[j] * inv + b2[lane * 4 + j];
        ss = fmaf(v[j], v[j], ss);
    }
    #pragma unroll
    for (int o = 16; o > 0; o >>= 1) ss += __shfl_xor_sync(0xffffffffu, ss, o);
    float nrm = sqrtf(ss);
    float scl = 1.0f / fmaxf(nrm, 1e-12f);
    float4 r = make_float4(v[0] * scl, v[1] * scl, v[2] * scl, v[3] * scl);
    *(float4*)(out + (size_t)node * 128 + lane * 4) = r;
}

// ---------------- host launcher ------------------------------------------------
extern "C" void kernel_launch(void* const* d_in, const int* in_sizes, int n_in,
                              void* d_out, int out_size)
{
    const float* x      = (const float*)d_in[0];
    const void*  eptr   = d_in[1];
    const float* W1     = (const float*)d_in[2];
    const float* a_src1 = (const float*)d_in[3];
    const float* a_dst1 = (const float*)d_in[4];
    const float* b1     = (const float*)d_in[5];
    const float* W2     = (const float*)d_in[6];
    const float* a_src2 = (const float*)d_in[7];
    const float* a_dst2 = (const float*)d_in[8];
    const float* b2     = (const float*)d_in[9];
    float* out = (float*)d_out;

    int n = in_sizes[0] / 128;    // 50000
    int E = in_sizes[1] / 2;      // 800000
    int tot = E + n;

    float *h1, *hact, *h2;
    cudaGetSymbolAddress((void**)&h1, g_h1);
    cudaGetSymbolAddress((void**)&hact, g_hact);
    cudaGetSymbolAddress((void**)&h2, g_h2);

    const int* e32 = (const int*)eptr;
    const long long* e64 = (const long long*)eptr;

    // CSR build
    detect_dtype_kernel<<<1, 32>>>(e32, E);
    zero_deg_kernel<<<(n + 255) / 256, 256>>>(n);
    histo_kernel<<<(tot + 255) / 256, 256>>>(e32, e64, E, n);
    scan_kernel<<<1, 1024>>>(n);
    scatter_kernel<<<(tot + 255) / 256, 256>>>(e32, e64, E, n);

    int nodeBlocks = (n + 7) / 8;

    // layer 1
    sgemm_kernel<<<dim3(256 / 64, (n + 127) / 128), 256>>>(x, W1, h1, n, 256, 128);
    alpha1_kernel<<<nodeBlocks, 256>>>(a_src1, a_dst1, n);
    agg1_kernel<<<nodeBlocks, 256>>>(b1, n);

    // layer 2
    sgemm_kernel<<<dim3(128 / 64, (n + 127) / 128), 256>>>(hact, W2, h2, n, 128, 256);
    alpha2_kernel<<<nodeBlocks, 256>>>(a_src2, a_dst2, n);
    agg2_kernel<<<nodeBlocks, 256>>>(b2, out, n);
}

// round 6
// speedup vs baseline: 1.0984x; 1.0984x over previous
#include <cuda_runtime.h>
#include <math.h>

#define NN 50000
#define NE 800000
#define ETOT (NE + NN)
#define MAXBLK 1024   // max 256-wide blocks for scan (supports up to 262144 nodes)

// ---------------- scratch (static device globals; no allocation) -------------
__device__ float g_h1[(size_t)NN * 256];    // layer1 projected features [N,4,64]
__device__ float g_hact[(size_t)NN * 256];  // layer1 output after elu
__device__ float g_h2[(size_t)NN * 128];    // layer2 projected features
__device__ float g_as1[NN * 4];
__device__ float g_ad1[NN * 4];
__device__ float g_as2[NN];
__device__ float g_ad2[NN];
__device__ int   g_deg[NN];
__device__ int   g_off[NN + 1];
__device__ int   g_fill[NN];
__device__ int   g_csr[ETOT];
__device__ int   g_is64;
__device__ int   g_blocksum[MAXBLK];
__device__ int   g_blockoff[MAXBLK];

// ---------------- edge dtype detection (int32 vs int64) ----------------------
__global__ void detect_dtype_kernel(const int* __restrict__ e32, int E) {
    int lim = (E > 1024) ? 1024 : E;
    int acc = 0;
    for (int k = threadIdx.x; k < lim; k += 32) acc |= e32[2 * k + 1];
    acc = __reduce_or_sync(0xffffffffu, acc);
    if (threadIdx.x == 0) g_is64 = (acc == 0) ? 1 : 0;  // int64 high words all zero
}

__device__ __forceinline__ int edge_src(const int* e32, const long long* e64, int E, int t) {
    if (t >= E) return t - E;                       // self loop
    return g_is64 ? (int)e64[t] : e32[t];
}
__device__ __forceinline__ int edge_dst(const int* e32, const long long* e64, int E, int t) {
    if (t >= E) return t - E;                       // self loop
    return g_is64 ? (int)e64[E + t] : e32[E + t];
}

// ---------------- CSR build ---------------------------------------------------
__global__ void zero_deg_kernel(int n) {
    int i = blockIdx.x * blockDim.x + threadIdx.x;
    if (i < n) g_deg[i] = 0;
}

__global__ void histo_kernel(const int* __restrict__ e32, const long long* __restrict__ e64,
                             int E, int n) {
    int t = blockIdx.x * blockDim.x + threadIdx.x;
    int tot = E + n;
    if (t < tot) {
        int d = edge_dst(e32, e64, E, t);
        atomicAdd(&g_deg[d], 1);
    }
}

// --- 3-phase multi-block exclusive scan of g_deg -> g_off / g_fill ------------
__global__ void scan_phaseA(int n) {   // per-block sums
    __shared__ int sh[256];
    int i = blockIdx.x * 256 + threadIdx.x;
    int v = (i < n) ? g_deg[i] : 0;
    sh[threadIdx.x] = v;
    __syncthreads();
    #pragma unroll
    for (int d = 128; d > 0; d >>= 1) {
        if (threadIdx.x < d) sh[threadIdx.x] += sh[threadIdx.x + d];
        __syncthreads();
    }
    if (threadIdx.x == 0) g_blocksum[blockIdx.x] = sh[0];
}

__global__ void scan_phaseB(int nb) {  // single small block scans the block sums
    __shared__ int sh[256];
    int carry = 0;
    for (int base = 0; base < nb; base += 256) {
        int t = base + threadIdx.x;
        int v = (t < nb) ? g_blocksum[t] : 0;
        sh[threadIdx.x] = v;
        __syncthreads();
        #pragma unroll
        for (int d = 1; d < 256; d <<= 1) {
            int u = (threadIdx.x >= d) ? sh[threadIdx.x - d] : 0;
            __syncthreads();
            sh[threadIdx.x] += u;
            __syncthreads();
        }
        if (t < nb) g_blockoff[t] = carry + sh[threadIdx.x] - v;
        carry += sh[255];
        __syncthreads();
    }
}

__global__ void scan_phaseC(int n) {   // per-block exclusive scan + global offset
    __shared__ int sh[256];
    int i = blockIdx.x * 256 + threadIdx.x;
    int v = (i < n) ? g_deg[i] : 0;
    sh[threadIdx.x] = v;
    __syncthreads();
    #pragma unroll
    for (int d = 1; d < 256; d <<= 1) {
        int u = (threadIdx.x >= d) ? sh[threadIdx.x - d] : 0;
        __syncthreads();
        sh[threadIdx.x] += u;
        __syncthreads();
    }
    int excl = g_blockoff[blockIdx.x] + sh[threadIdx.x] - v;
    if (i < n) {
        g_off[i]  = excl;
        g_fill[i] = excl;
        if (i == n - 1) g_off[n] = excl + v;
    }
}

__global__ void scatter_kernel(const int* __restrict__ e32, const long long* __restrict__ e64,
                               int E, int n) {
    int t = blockIdx.x * blockDim.x + threadIdx.x;
    int tot = E + n;
    if (t < tot) {
        int s = edge_src(e32, e64, E, t);
        int d = edge_dst(e32, e64, E, t);
        int pos = atomicAdd(&g_fill[d], 1);
        g_csr[pos] = s;
    }
}

// ---------------- SGEMM: C[M,N] = A[M,K] @ B[K,N] (row major) ----------------
// BM=BN=128, BK=8, 256 threads, 8x8 micro-tile, 4x2 warp grid. N%128==0, K%8==0.
__global__ __launch_bounds__(256, 2) void sgemm128_kernel(
    const float* __restrict__ A, const float* __restrict__ B, float* __restrict__ C,
    int M, int N, int K)
{
    __shared__ float As[8][128];
    __shared__ float Bs[8][128];

    int tid = threadIdx.x;
    int w = tid >> 5, lane = tid & 31;
    int wr = w & 3, wc = w >> 2;        // warp row 0..3, warp col 0..1
    int lr = lane >> 3, lc = lane & 7;  // 4x8 lanes within warp
    int rowBase = blockIdx.y * 128;
    int colBase = blockIdx.x * 128;
    int tRow = wr * 32 + lr * 8;        // thread row offset within tile
    int tCol = wc * 64 + lc * 8;        // thread col offset within tile

    float acc[8][8];
    #pragma unroll
    for (int i = 0; i < 8; ++i)
        #pragma unroll
        for (int j = 0; j < 8; ++j) acc[i][j] = 0.f;

    int ar = tid >> 1;             // 0..127
    int ak = (tid & 1) * 4;        // 0 or 4
    int br = tid >> 5;             // 0..7
    int bc = (tid & 31) * 4;       // 0..124

    for (int k0 = 0; k0 < K; k0 += 8) {
        int grow = rowBase + ar;
        float4 av = make_float4(0.f, 0.f, 0.f, 0.f);
        if (grow < M) av = *(const float4*)(A + (size_t)grow * K + k0 + ak);
        As[ak + 0][ar] = av.x;
        As[ak + 1][ar] = av.y;
        As[ak + 2][ar] = av.z;
        As[ak + 3][ar] = av.w;
        *(float4*)&Bs[br][bc] = *(const float4*)(B + (size_t)(k0 + br) * N + colBase + bc);
        __syncthreads();
        #pragma unroll
        for (int kk = 0; kk < 8; ++kk) {
            float a[8], b[8];
            *(float4*)&a[0] = *(const float4*)&As[kk][tRow];
            *(float4*)&a[4] = *(const float4*)&As[kk][tRow + 4];
            *(float4*)&b[0] = *(const float4*)&Bs[kk][tCol];
            *(float4*)&b[4] = *(const float4*)&Bs[kk][tCol + 4];
            #pragma unroll
            for (int i = 0; i < 8; ++i)
                #pragma unroll
                for (int j = 0; j < 8; ++j)
                    acc[i][j] = fmaf(a[i], b[j], acc[i][j]);
        }
        __syncthreads();
    }

    #pragma unroll
    for (int i = 0; i < 8; ++i) {
        int r = rowBase + tRow + i;
        if (r < M) {
            float4 v0 = make_float4(acc[i][0], acc[i][1], acc[i][2], acc[i][3]);
            float4 v1 = make_float4(acc[i][4], acc[i][5], acc[i][6], acc[i][7]);
            *(float4*)(C + (size_t)r * N + colBase + tCol)     = v0;
            *(float4*)(C + (size_t)r * N + colBase + tCol + 4) = v1;
        }
    }
}

// ---------------- per-node attention coefficients -----------------------------
// layer 1: 4 heads x 64 dims; one warp per node; lane owns cols lane*8..+7
__global__ __launch_bounds__(256) void alpha1_kernel(
    const float* __restrict__ a_src, const float* __restrict__ a_dst, int n)
{
    __shared__ float sa[256], sd[256];
    sa[threadIdx.x] = a_src[threadIdx.x];
    sd[threadIdx.x] = a_dst[threadIdx.x];
    __syncthreads();
    int node = (blockIdx.x << 3) + (threadIdx.x >> 5);
    if (node >= n) return;
    int lane = threadIdx.x & 31;
    int c0 = lane * 8;
    const float4* p = (const float4*)(g_h1 + (size_t)node * 256 + c0);
    float4 v0 = p[0], v1 = p[1];
    float hv[8] = {v0.x, v0.y, v0.z, v0.w, v1.x, v1.y, v1.z, v1.w};
    float ps = 0.f, pd = 0.f;
    #pragma unroll
    for (int j = 0; j < 8; ++j) {
        ps = fmaf(hv[j], sa[c0 + j], ps);
        pd = fmaf(hv[j], sd[c0 + j], pd);
    }
    #pragma unroll
    for (int o = 1; o < 8; o <<= 1) {
        ps += __shfl_xor_sync(0xffffffffu, ps, o);
        pd += __shfl_xor_sync(0xffffffffu, pd, o);
    }
    if ((lane & 7) == 0) {
        int h = lane >> 3;
        g_as1[node * 4 + h] = ps;
        g_ad1[node * 4 + h] = pd;
    }
}

// layer 2: 1 head x 128 dims; lane owns cols lane*4..+3
__global__ __launch_bounds__(256) void alpha2_kernel(
    const float* __restrict__ a_src, const float* __restrict__ a_dst, int n)
{
    __shared__ float sa[128], sd[128];
    if (threadIdx.x < 128) {
        sa[threadIdx.x] = a_src[threadIdx.x];
        sd[threadIdx.x] = a_dst[threadIdx.x];
    }
    __syncthreads();
    int node = (blockIdx.x << 3) + (threadIdx.x >> 5);
    if (node >= n) return;
    int lane = threadIdx.x & 31;
    int c0 = lane * 4;
    float4 v = *(const float4*)(g_h2 + (size_t)node * 128 + c0);
    float ps = v.x * sa[c0] + v.y * sa[c0 + 1] + v.z * sa[c0 + 2] + v.w * sa[c0 + 3];
    float pd = v.x * sd[c0] + v.y * sd[c0 + 1] + v.z * sd[c0 + 2] + v.w * sd[c0 + 3];
    #pragma unroll
    for (int o = 1; o < 32; o <<= 1) {
        ps += __shfl_xor_sync(0xffffffffu, ps, o);
        pd += __shfl_xor_sync(0xffffffffu, pd, o);
    }
    if (lane == 0) {
        g_as2[node] = ps;
        g_ad2[node] = pd;
    }
}

__device__ __forceinline__ float lrelu(float x) { return fmaxf(x, 0.2f * x); }

// ---------------- layer-1 aggregation: warp per node, softmax + weighted sum --
__global__ __launch_bounds__(256) void agg1_kernel(const float* __restrict__ b1, int n)
{
    int node = (blockIdx.x << 3) + (threadIdx.x >> 5);
    if (node >= n) return;
    int lane = threadIdx.x & 31;
    int s = g_off[node], e = g_off[node + 1];
    int h = lane >> 3;  // head owned by this lane

    float ad[4];
    #pragma unroll
    for (int hh = 0; hh < 4; ++hh) ad[hh] = g_ad1[node * 4 + hh];

    // pass 1: per-head max over incoming edges
    float mx[4] = {-1e30f, -1e30f, -1e30f, -1e30f};
    for (int i = s + lane; i < e; i += 32) {
        int src = g_csr[i];
        const float* asv = g_as1 + src * 4;
        #pragma unroll
        for (int hh = 0; hh < 4; ++hh) {
            float lg = lrelu(asv[hh] + ad[hh]);
            mx[hh] = fmaxf(mx[hh], lg);
        }
    }
    #pragma unroll
    for (int o = 16; o > 0; o >>= 1)
        #pragma unroll
        for (int hh = 0; hh < 4; ++hh)
            mx[hh] = fmaxf(mx[hh], __shfl_xor_sync(0xffffffffu, mx[hh], o));
    float mh = mx[h];
    float adh = ad[h];

    // pass 2: weighted accumulation; lane owns cols lane*8..lane*8+7 (all head h)
    float acc[8] = {0, 0, 0, 0, 0, 0, 0, 0};
    float denom = 0.f;
    for (int i = s; i < e; ++i) {
        int src = g_csr[i];
        float lg = lrelu(g_as1[src * 4 + h] + adh);
        float w = __expf(lg - mh);
        denom += w;
        const float4* p = (const float4*)(g_h1 + (size_t)src * 256 + lane * 8);
        float4 v0 = p[0], v1 = p[1];
        acc[0] = fmaf(w, v0.x, acc[0]);
        acc[1] = fmaf(w, v0.y, acc[1]);
        acc[2] = fmaf(w, v0.z, acc[2]);
        acc[3] = fmaf(w, v0.w, acc[3]);
        acc[4] = fmaf(w, v1.x, acc[4]);
        acc[5] = fmaf(w, v1.y, acc[5]);
        acc[6] = fmaf(w, v1.z, acc[6]);
        acc[7] = fmaf(w, v1.w, acc[7]);
    }
    float inv = 1.0f / (denom + 1e-16f);
    #pragma unroll
    for (int j = 0; j < 8; ++j) {
        int c = lane * 8 + j;
        float v = acc[j] * inv + b1[c];
        v = (v > 0.f) ? v : expm1f(v);  // elu
        g_hact[(size_t)node * 256 + c] = v;
    }
}

// ---------------- layer-2 aggregation + L2-normalize epilogue ------------------
__global__ __launch_bounds__(256) void agg2_kernel(
    const float* __restrict__ b2, float* __restrict__ out, int n)
{
    int node = (blockIdx.x << 3) + (threadIdx.x >> 5);
    if (node >= n) return;
    int lane = threadIdx.x & 31;
    int s = g_off[node], e = g_off[node + 1];

    float ad = g_ad2[node];
    float mx = -1e30f;
    for (int i = s + lane; i < e; i += 32) {
        int src = g_csr[i];
        mx = fmaxf(mx, lrelu(g_as2[src] + ad));
    }
    #pragma unroll
    for (int o = 16; o > 0; o >>= 1)
        mx = fmaxf(mx, __shfl_xor_sync(0xffffffffu, mx, o));

    float acc[4] = {0, 0, 0, 0};
    float denom = 0.f;
    for (int i = s; i < e; ++i) {
        int src = g_csr[i];
        float lg = lrelu(g_as2[src] + ad);
        float w = __expf(lg - mx);
        denom += w;
        float4 v = *(const float4*)(g_h2 + (size_t)src * 128 + lane * 4);
        acc[0] = fmaf(w, v.x, acc[0]);
        acc[1] = fmaf(w, v.y, acc[1]);
        acc[2] = fmaf(w, v.z, acc[2]);
        acc[3] = fmaf(w, v.w, acc[3]);
    }
    float inv = 1.0f / (denom + 1e-16f);
    float v[4];
    float ss = 0.f;
    #pragma unroll
    for (int j = 0; j < 4; ++j) {
        v[j] = acc[j] * inv + b2[lane * 4 + j];
        ss = fmaf(v[j], v[j], ss);
    }
    #pragma unroll
    for (int o = 16; o > 0; o >>= 1) ss += __shfl_xor_sync(0xffffffffu, ss, o);
    float nrm = sqrtf(ss);
    float scl = 1.0f / fmaxf(nrm, 1e-12f);
    float4 r = make_float4(v[0] * scl, v[1] * scl, v[2] * scl, v[3] * scl);
    *(float4*)(out + (size_t)node * 128 + lane * 4) = r;
}

// ---------------- host launcher ------------------------------------------------
extern "C" void kernel_launch(void* const* d_in, const int* in_sizes, int n_in,
                              void* d_out, int out_size)
{
    const float* x      = (const float*)d_in[0];
    const void*  eptr   = d_in[1];
    const float* W1     = (const float*)d_in[2];
    const float* a_src1 = (const float*)d_in[3];
    const float* a_dst1 = (const float*)d_in[4];
    const float* b1     = (const float*)d_in[5];
    const float* W2     = (const float*)d_in[6];
    const float* a_src2 = (const float*)d_in[7];
    const float* a_dst2 = (const float*)d_in[8];
    const float* b2     = (const float*)d_in[9];
    float* out = (float*)d_out;

    int n = in_sizes[0] / 128;    // 50000
    int E = in_sizes[1] / 2;      // 800000
    int tot = E + n;

    float *h1, *hact, *h2;
    cudaGetSymbolAddress((void**)&h1, g_h1);
    cudaGetSymbolAddress((void**)&hact, g_hact);
    cudaGetSymbolAddress((void**)&h2, g_h2);

    const int* e32 = (const int*)eptr;
    const long long* e64 = (const long long*)eptr;

    int nb = (n + 255) / 256;

    // CSR build
    detect_dtype_kernel<<<1, 32>>>(e32, E);
    zero_deg_kernel<<<nb, 256>>>(n);
    histo_kernel<<<(tot + 255) / 256, 256>>>(e32, e64, E, n);
    scan_phaseA<<<nb, 256>>>(n);
    scan_phaseB<<<1, 256>>>(nb);
    scan_phaseC<<<nb, 256>>>(n);
    scatter_kernel<<<(tot + 255) / 256, 256>>>(e32, e64, E, n);

    int nodeBlocks = (n + 7) / 8;

    // layer 1
    sgemm128_kernel<<<dim3(256 / 128, (n + 127) / 128), 256>>>(x, W1, h1, n, 256, 128);
    alpha1_kernel<<<nodeBlocks, 256>>>(a_src1, a_dst1, n);
    agg1_kernel<<<nodeBlocks, 256>>>(b1, n);

    // layer 2
    sgemm128_kernel<<<dim3(128 / 128, (n + 127) / 128), 256>>>(hact, W2, h2, n, 128, 256);
    alpha2_kernel<<<nodeBlocks, 256>>>(a_src2, a_dst2, n);
    agg2_kernel<<<nodeBlocks, 256>>>(b2, out, n);
}